// round 6
// baseline (speedup 1.0000x reference)
#include <cuda_runtime.h>
#include <cuda_bf16.h>

// SEIR Euler integration, two-phase checkpoint scheme, checkpoints in-place.
//
// Phase 1: B threads integrate all t steps compute-only (serial chain),
//          writing chunk-boundary states directly into their final out[] slot
//          with DEFAULT store policy (L2-resident for phase 2's re-read).
// Phase 2: (t/CHUNK)*B threads re-load their chunk-start state (L2 hot) and
//          stream-store the remaining CHUNK-1 steps.
//
// Round-5 profile: occ 87.3%, DRAM 68.4%, 10.3us serial prologue.
// This round: CHUNK 32->16 (2M phase-2 threads), shorter fma chain.

#define CHUNK 16

// One Euler step with pre-scaled rates (bh = beta*step, etc.).
// Written to minimize the loop-carried dependence chain:
//   p  = bh*S                (off the I-path)
//   Sn = fma(-p, I, S)
//   En = fma( p, I, fma(-sh, E, E))
//   In = fma( sh, E, fma(-gh, I, I))
//   Rn = fma( gh, I, R)
__device__ __forceinline__ float4 seir_step(float4 v, float bh, float gh, float sh)
{
    const float S = v.x, E = v.y, I = v.z, R = v.w;
    const float p = bh * S;
    float4 r;
    r.x = __fmaf_rn(-p, I, S);
    r.y = __fmaf_rn( p, I, __fmaf_rn(-sh, E, E));
    r.z = __fmaf_rn( sh, E, __fmaf_rn(-gh, I, I));
    r.w = __fmaf_rn( gh, I, R);
    return r;
}

// ---- Phase 1: compute + store chunk-boundary states (in-place checkpoints) ----
__global__ void __launch_bounds__(128) seir_ckpt_kernel(
    const float* __restrict__ initial,
    const float* __restrict__ beta,
    const float* __restrict__ gamma,
    const float* __restrict__ sigma,
    float4* __restrict__ out,
    int B, int t)
{
    const int b = blockIdx.x * blockDim.x + threadIdx.x;
    if (b >= B) return;

    const float step = 0.5f;
    const float bh = beta[0]  * step;
    const float gh = gamma[0] * step;
    const float sh = sigma[0] * step;

    float4 v = make_float4(initial[0 * B + b], initial[1 * B + b],
                           initial[2 * B + b], initial[3 * B + b]);
    out[b] = v;  // state at step 0 (final position, default policy -> L2)

    const int nchunks = (t + CHUNK - 1) / CHUNK;
    for (int c = 1; c < nchunks; ++c) {
        #pragma unroll
        for (int j = 0; j < CHUNK; ++j)
            v = seir_step(v, bh, gh, sh);
        out[(size_t)c * CHUNK * B + b] = v;  // state at step c*CHUNK
    }
}

// ---- Phase 2: each thread fills the CHUNK-1 remaining steps of one chunk ----
__global__ void __launch_bounds__(256) seir_store_kernel(
    const float* __restrict__ beta,
    const float* __restrict__ gamma,
    const float* __restrict__ sigma,
    float4* __restrict__ out,
    int B, int t)
{
    const int tid = blockIdx.x * blockDim.x + threadIdx.x;
    const int c  = tid / B;
    const int bb = tid - c * B;

    const int n0 = c * CHUNK;
    if (n0 >= t || bb >= B) return;

    const float step = 0.5f;
    const float bh = beta[0]  * step;
    const float gh = gamma[0] * step;
    const float sh = sigma[0] * step;

    size_t idx = (size_t)n0 * B + bb;
    float4 v = out[idx];                    // chunk-start state (L2 hot)

    const int nlast = min(n0 + CHUNK, t);
    if (nlast == n0 + CHUNK) {
        #pragma unroll
        for (int j = 1; j < CHUNK; ++j) {
            v = seir_step(v, bh, gh, sh);
            idx += B;
            __stcs(&out[idx], v);           // state at step n0+j
        }
    } else {
        for (int n = n0 + 1; n < nlast; ++n) {
            v = seir_step(v, bh, gh, sh);
            idx += B;
            __stcs(&out[idx], v);
        }
    }
}

extern "C" void kernel_launch(void* const* d_in, const int* in_sizes, int n_in,
                              void* d_out, int out_size)
{
    const float* initial = (const float*)d_in[0];   // 4*B elements
    const float* beta    = (const float*)d_in[1];
    const float* gamma   = (const float*)d_in[2];
    const float* sigma   = (const float*)d_in[3];

    const int B = in_sizes[0] / 4;
    const int t = (B > 0) ? (out_size / (4 * B)) : 0;
    if (B <= 0 || t <= 0) return;

    const int nchunks = (t + CHUNK - 1) / CHUNK;

    // Phase 1: checkpoints straight into the output (chain-latency bound)
    seir_ckpt_kernel<<<(B + 127) / 128, 128>>>(initial, beta, gamma, sigma,
                                               (float4*)d_out, B, t);
    // Phase 2: parallel-in-time fill of the remaining steps (DRAM-bound)
    const long long total = (long long)nchunks * B;
    const int grid = (int)((total + 255) / 256);
    seir_store_kernel<<<grid, 256>>>(beta, gamma, sigma, (float4*)d_out, B, t);
}